// round 5
// baseline (speedup 1.0000x reference)
#include <cuda_runtime.h>
#include <math.h>
#include <stdint.h>

#define NTOK 8192
#define DDIM 1024
#define FDIM 2816
#define NEXP 8
#define CAP  8192

// ---------------- device scratch ----------------
__device__ int   g_count[NEXP];
__device__ int   g_tok[NEXP * CAP];
__device__ int   g_slot[NTOK * 2];
__device__ float g_wt[NTOK * 2];
__device__ float g_act[(size_t)NEXP * CAP * FDIM];
__device__ float g_y[(size_t)NEXP * CAP * DDIM];

// ---------------- helpers ----------------
__device__ __forceinline__ uint32_t smem_u32(const void* p) {
    uint32_t a;
    asm("{ .reg .u64 t; cvta.to.shared.u64 t, %1; cvt.u32.u64 %0, t; }" : "=r"(a) : "l"(p));
    return a;
}
__device__ __forceinline__ uint32_t cvt_tf32(float x) {
    uint32_t r; asm("cvt.rna.tf32.f32 %0, %1;" : "=r"(r) : "f"(x)); return r;
}

#define CPA(dst, src, n) asm volatile("cp.async.cg.shared.global [%0], [%1], 16, %2;" :: "r"(dst), "l"(src), "r"(n) : "memory")
#define CPA_COMMIT()     asm volatile("cp.async.commit_group;" ::: "memory")
#define CPA_WAIT1()      asm volatile("cp.async.wait_group 1;" ::: "memory")

#define MMA_TF32(d, a, b) \
    asm volatile("mma.sync.aligned.m16n8k8.row.col.f32.tf32.tf32.f32 " \
        "{%0,%1,%2,%3}, {%4,%5,%6,%7}, {%8,%9}, {%0,%1,%2,%3};" \
        : "+f"((d)[0]), "+f"((d)[1]), "+f"((d)[2]), "+f"((d)[3]) \
        : "r"((a)[0]), "r"((a)[1]), "r"((a)[2]), "r"((a)[3]), "r"((b)[0]), "r"((b)[1]))

// ---------------- kernel 0: reset ----------------
__global__ void reset_kernel() {
    if (threadIdx.x < NEXP) g_count[threadIdx.x] = 0;
}

// ---------------- kernel 1: router ----------------
__global__ void router_kernel(const float* __restrict__ X, const float* __restrict__ RW) {
    __shared__ float sW[NEXP * DDIM];
    const int tid = threadIdx.x;
    for (int i = tid; i < NEXP * DDIM; i += 128) {
        int d = i >> 3, e = i & 7;
        sW[e * DDIM + d] = RW[i];
    }
    __syncthreads();
    const int warp = tid >> 5, lane = tid & 31;
    const int t = blockIdx.x * 4 + warp;
    const float* xr = X + (size_t)t * DDIM;
    float acc[NEXP];
#pragma unroll
    for (int e = 0; e < NEXP; e++) acc[e] = 0.f;
    for (int d = lane; d < DDIM; d += 32) {
        float xv = xr[d];
#pragma unroll
        for (int e = 0; e < NEXP; e++) acc[e] += xv * sW[e * DDIM + d];
    }
#pragma unroll
    for (int e = 0; e < NEXP; e++)
#pragma unroll
        for (int off = 16; off > 0; off >>= 1)
            acc[e] += __shfl_xor_sync(0xFFFFFFFFu, acc[e], off);
    if (lane == 0) {
        int i0 = 0; float s0 = acc[0];
#pragma unroll
        for (int e = 1; e < NEXP; e++) if (acc[e] > s0) { s0 = acc[e]; i0 = e; }
        int i1 = -1; float s1 = -INFINITY;
#pragma unroll
        for (int e = 0; e < NEXP; e++) if (e != i0 && acc[e] > s1) { s1 = acc[e]; i1 = e; }
        float w0 = 1.f / (1.f + expf(s1 - s0));
        float w1 = 1.f - w0;
        int p0 = atomicAdd(&g_count[i0], 1);
        int p1 = atomicAdd(&g_count[i1], 1);
        g_tok[i0 * CAP + p0] = t;
        g_tok[i1 * CAP + p1] = t;
        g_slot[2 * t + 0] = i0 * CAP + p0;  g_wt[2 * t + 0] = w0;
        g_slot[2 * t + 1] = i1 * CAP + p1;  g_wt[2 * t + 1] = w1;
    }
}

// ================= tf32 mma.sync GEMMs (512 threads, 16 warps) =================

// ---------------- kernel 2: fused gate+up + SiLU (split-warp) ----------------
// CTA 128x128x32. Warps 0-7: gate GEMM (2M x 4N, warp 64x32). Warps 8-15: up GEMM.
__global__ void __launch_bounds__(512, 1)
gateup_mma_kernel(const float* __restrict__ X,
                  const float* __restrict__ Wg,
                  const float* __restrict__ Wu) {
    extern __shared__ float smem[];
    float* As  = smem;              // 3 * 4096 floats
    float* Bgs = smem + 12288;
    float* Bus = smem + 24576;

    const int e = blockIdx.z;
    const int cnt = g_count[e];
    const int m0 = blockIdx.x * 128;
    if (m0 >= cnt) return;
    const int n0 = blockIdx.y * 128;

    const int tid = threadIdx.x, wid = tid >> 5, lane = tid & 31;
    const bool is_gate = wid < 8;
    const int w = wid & 7;
    const int wm = w & 1, wn = w >> 1;
    const int lr = lane >> 2, lc = lane & 3;

    // A gmem->smem: 512 threads, row = tid>>2, 2 chunks of 16B each
    const int ar = tid >> 2;
    const bool av = (m0 + ar) < cnt;
    const float* arow = X + (size_t)(av ? g_tok[e * CAP + m0 + ar] : 0) * DDIM;
    const int an = av ? 16 : 0;
    uint32_t aoff[2]; int ac[2];
#pragma unroll
    for (int i = 0; i < 2; i++) {
        int c = (tid & 3) + 4 * i;
        ac[i] = c;
        aoff[i] = (uint32_t)(ar * 128 + ((c ^ (ar & 7)) << 4));
    }
    // B gmem->smem: k-row = tid>>4 (0..31), 2 chunks each for G and U
    const int bk = tid >> 4;
    const float* grow = Wg + ((size_t)e * DDIM + bk) * FDIM + n0;
    const float* urow = Wu + ((size_t)e * DDIM + bk) * FDIM + n0;
    uint32_t boff[2]; int bc[2];
#pragma unroll
    for (int i = 0; i < 2; i++) {
        int c = (tid & 15) + 16 * i;
        bc[i] = c;
        boff[i] = (uint32_t)(bk * 512 + ((c ^ ((bk & 3) << 1)) << 4));
    }

    const uint32_t sA = smem_u32(As), sG = smem_u32(Bgs), sU = smem_u32(Bus);
    const float* Bmine = is_gate ? Bgs : Bus;

    float acc[4][4][4];
#pragma unroll
    for (int mi = 0; mi < 4; mi++)
#pragma unroll
        for (int ni = 0; ni < 4; ni++)
#pragma unroll
            for (int q = 0; q < 4; q++) acc[mi][ni][q] = 0.f;

    const int KT = DDIM / 32;   // 32

#define GU_PREFETCH(s) do { \
    int _buf = (s) % 3; \
    uint32_t _da = sA + _buf * 16384, _dg = sG + _buf * 16384, _du = sU + _buf * 16384; \
    const float* _ap = arow + (s) * 32; \
    const float* _gp = grow + (size_t)(s) * 32 * FDIM; \
    const float* _up = urow + (size_t)(s) * 32 * FDIM; \
    _Pragma("unroll") \
    for (int _i = 0; _i < 2; _i++) { \
        CPA(_da + aoff[_i], _ap + ac[_i] * 4, an); \
        CPA(_dg + boff[_i], _gp + bc[_i] * 4, 16); \
        CPA(_du + boff[_i], _up + bc[_i] * 4, 16); \
    } } while (0)

    GU_PREFETCH(0); CPA_COMMIT();
    GU_PREFETCH(1); CPA_COMMIT();

    for (int s = 0; s < KT; s++) {
        CPA_WAIT1();
        __syncthreads();
        if (s + 2 < KT) { GU_PREFETCH(s + 2); }
        CPA_COMMIT();
        const int buf = s % 3;
        const float* A = As + buf * 4096;
        const float* B = Bmine + buf * 4096;
#pragma unroll
        for (int k8 = 0; k8 < 4; k8++) {
            uint32_t a[4][4];
#pragma unroll
            for (int mi = 0; mi < 4; mi++) {
                const int r0 = wm * 64 + mi * 16 + lr;
#pragma unroll
                for (int h = 0; h < 2; h++) {
                    const int cx = (((2 * k8 + h) ^ lr) << 2) + lc;
                    a[mi][h * 2 + 0] = cvt_tf32(A[r0 * 32 + cx]);
                    a[mi][h * 2 + 1] = cvt_tf32(A[(r0 + 8) * 32 + cx]);
                }
            }
#pragma unroll
            for (int ni = 0; ni < 4; ni++) {
                const int c = wn * 8 + ni * 2 + (lr >> 2);
                const int bx = ((c ^ (lc << 1)) << 2) + (lr & 3);
                uint32_t b[2];
#pragma unroll
                for (int h = 0; h < 2; h++)
                    b[h] = cvt_tf32(B[(k8 * 8 + lc + 4 * h) * 128 + bx]);
#pragma unroll
                for (int mi = 0; mi < 4; mi++)
                    MMA_TF32(acc[mi][ni], a[mi], b);
            }
        }
    }

    // epilogue: gate warps stage silu(g) in smem; up warps multiply and store.
    __syncthreads();    // all MMAs done before overwriting smem
    float* st = smem;   // 128 x 132 staging
    if (is_gate) {
#pragma unroll
        for (int mi = 0; mi < 4; mi++) {
            const int r = wm * 64 + mi * 16 + lr;
#pragma unroll
            for (int ni = 0; ni < 4; ni++) {
                const int col = wn * 32 + ni * 8 + 2 * lc;
                float g0 = acc[mi][ni][0], g1 = acc[mi][ni][1];
                float g2 = acc[mi][ni][2], g3 = acc[mi][ni][3];
                float2 v0, v1;
                v0.x = g0 / (1.f + __expf(-g0));
                v0.y = g1 / (1.f + __expf(-g1));
                v1.x = g2 / (1.f + __expf(-g2));
                v1.y = g3 / (1.f + __expf(-g3));
                *(float2*)&st[r * 132 + col] = v0;
                *(float2*)&st[(r + 8) * 132 + col] = v1;
            }
        }
    }
    __syncthreads();
    if (!is_gate) {
#pragma unroll
        for (int mi = 0; mi < 4; mi++) {
            const int r = wm * 64 + mi * 16 + lr;
            const size_t row0 = (size_t)e * CAP + m0 + r;
#pragma unroll
            for (int ni = 0; ni < 4; ni++) {
                const int col = wn * 32 + ni * 8 + 2 * lc;
                if (m0 + r < cnt) {
                    float2 s0 = *(const float2*)&st[r * 132 + col];
                    float2 v;
                    v.x = s0.x * acc[mi][ni][0];
                    v.y = s0.y * acc[mi][ni][1];
                    *(float2*)&g_act[row0 * FDIM + n0 + col] = v;
                }
                if (m0 + r + 8 < cnt) {
                    float2 s1 = *(const float2*)&st[(r + 8) * 132 + col];
                    float2 v;
                    v.x = s1.x * acc[mi][ni][2];
                    v.y = s1.y * acc[mi][ni][3];
                    *(float2*)&g_act[(row0 + 8) * FDIM + n0 + col] = v;
                }
            }
        }
    }
}

// ---------------- kernel 3: down GEMM ----------------
// CTA 128x256x32, 16 warps (2M x 8N), warp tile 64x32.
__global__ void __launch_bounds__(512, 1)
down_mma_kernel(const float* __restrict__ Wd) {
    extern __shared__ float smem[];
    float* As = smem;               // 3 * 4096 floats
    float* Bs = smem + 12288;       // 3 * 8192 floats

    const int e = blockIdx.z;
    const int cnt = g_count[e];
    const int m0 = blockIdx.x * 128;
    if (m0 >= cnt) return;
    const int n0 = blockIdx.y * 256;

    const int tid = threadIdx.x, wid = tid >> 5, lane = tid & 31;
    const int wm = wid & 1, wn = wid >> 1;   // wn in 0..7, 32-col slabs
    const int lr = lane >> 2, lc = lane & 3;

    // A: row = tid>>2, 2 chunks
    const int ar = tid >> 2;
    const bool av = (m0 + ar) < cnt;
    const float* arow = g_act + ((size_t)e * CAP + m0 + (av ? ar : 0)) * FDIM;
    const int an = av ? 16 : 0;
    uint32_t aoff[2]; int ac[2];
#pragma unroll
    for (int i = 0; i < 2; i++) {
        int c = (tid & 3) + 4 * i;
        ac[i] = c;
        aoff[i] = (uint32_t)(ar * 128 + ((c ^ (ar & 7)) << 4));
    }
    // B: k-row = tid>>4 (0..31), 4 chunks along n (256 floats = 64 chunks)
    const int bk = tid >> 4;
    const float* brow = Wd + ((size_t)e * FDIM + bk) * DDIM + n0;
    uint32_t boff[4]; int bc[4];
#pragma unroll
    for (int i = 0; i < 4; i++) {
        int c = (tid & 15) + 16 * i;
        bc[i] = c;
        boff[i] = (uint32_t)(bk * 1024 + ((c ^ ((bk & 3) << 1)) << 4));
    }

    const uint32_t sA = smem_u32(As), sB = smem_u32(Bs);

    float acc[4][4][4];
#pragma unroll
    for (int mi = 0; mi < 4; mi++)
#pragma unroll
        for (int ni = 0; ni < 4; ni++)
#pragma unroll
            for (int q = 0; q < 4; q++) acc[mi][ni][q] = 0.f;

    const int KT = FDIM / 32;   // 88

#define DN_PREFETCH(s) do { \
    int _buf = (s) % 3; \
    uint32_t _da = sA + _buf * 16384, _db = sB + _buf * 32768; \
    const float* _ap = arow + (s) * 32; \
    const float* _bp = brow + (size_t)(s) * 32 * DDIM; \
    _Pragma("unroll") \
    for (int _i = 0; _i < 2; _i++) CPA(_da + aoff[_i], _ap + ac[_i] * 4, an); \
    _Pragma("unroll") \
    for (int _i = 0; _i < 4; _i++) CPA(_db + boff[_i], _bp + bc[_i] * 4, 16); \
    } while (0)

    DN_PREFETCH(0); CPA_COMMIT();
    DN_PREFETCH(1); CPA_COMMIT();

    for (int s = 0; s < KT; s++) {
        CPA_WAIT1();
        __syncthreads();
        if (s + 2 < KT) { DN_PREFETCH(s + 2); }
        CPA_COMMIT();
        const int buf = s % 3;
        const float* A = As + buf * 4096;
        const float* B = Bs + buf * 8192;
#pragma unroll
        for (int k8 = 0; k8 < 4; k8++) {
            uint32_t a[4][4];
#pragma unroll
            for (int mi = 0; mi < 4; mi++) {
                const int r0 = wm * 64 + mi * 16 + lr;
#pragma unroll
                for (int h = 0; h < 2; h++) {
                    const int cx = (((2 * k8 + h) ^ lr) << 2) + lc;
                    a[mi][h * 2 + 0] = cvt_tf32(A[r0 * 32 + cx]);
                    a[mi][h * 2 + 1] = cvt_tf32(A[(r0 + 8) * 32 + cx]);
                }
            }
#pragma unroll
            for (int ni = 0; ni < 4; ni++) {
                const int cidx = wn * 8 + ni * 2 + (lr >> 2);
                const int bx = ((cidx ^ (lc << 1)) << 2) + (lr & 3);
                uint32_t b[2];
#pragma unroll
                for (int h = 0; h < 2; h++)
                    b[h] = cvt_tf32(B[(k8 * 8 + lc + 4 * h) * 256 + bx]);
#pragma unroll
                for (int mi = 0; mi < 4; mi++)
                    MMA_TF32(acc[mi][ni], a[mi], b);
            }
        }
    }

#pragma unroll
    for (int mi = 0; mi < 4; mi++) {
        const int r = wm * 64 + mi * 16 + lr;
        const size_t row0 = (size_t)e * CAP + m0 + r;
#pragma unroll
        for (int ni = 0; ni < 4; ni++) {
            const int col = n0 + wn * 32 + ni * 8 + 2 * lc;
            if (m0 + r < cnt) {
                float2 v; v.x = acc[mi][ni][0]; v.y = acc[mi][ni][1];
                *(float2*)&g_y[row0 * DDIM + col] = v;
            }
            if (m0 + r + 8 < cnt) {
                float2 v; v.x = acc[mi][ni][2]; v.y = acc[mi][ni][3];
                *(float2*)&g_y[(row0 + 8) * DDIM + col] = v;
            }
        }
    }
}

// ---------------- kernel 4: weighted combine ----------------
__global__ void combine_kernel(float* __restrict__ out) {
    const int g = blockIdx.x * blockDim.x + threadIdx.x;
    const int t = g >> 8;
    const int c = g & 255;
    const int s0 = g_slot[2 * t], s1 = g_slot[2 * t + 1];
    const float w0 = g_wt[2 * t], w1 = g_wt[2 * t + 1];
    const float4* Y = (const float4*)g_y;
    float4 a = Y[(size_t)s0 * 256 + c];
    float4 b = Y[(size_t)s1 * 256 + c];
    float4 o;
    o.x = w0 * a.x + w1 * b.x;
    o.y = w0 * a.y + w1 * b.y;
    o.z = w0 * a.z + w1 * b.z;
    o.w = w0 * a.w + w1 * b.w;
    ((float4*)out)[g] = o;
}

// ---------------- launch ----------------
extern "C" void kernel_launch(void* const* d_in, const int* in_sizes, int n_in,
                              void* d_out, int out_size) {
    const float* x  = (const float*)d_in[0];
    const float* rw = (const float*)d_in[1];
    const float* wg = (const float*)d_in[2];
    const float* wu = (const float*)d_in[3];
    const float* wd = (const float*)d_in[4];
    float* out = (float*)d_out;

    cudaFuncSetAttribute(gateup_mma_kernel, cudaFuncAttributeMaxDynamicSharedMemorySize, 147456);
    cudaFuncSetAttribute(down_mma_kernel,   cudaFuncAttributeMaxDynamicSharedMemorySize, 147456);

    reset_kernel<<<1, 32>>>();
    router_kernel<<<NTOK / 4, 128>>>(x, rw);

    gateup_mma_kernel<<<dim3(CAP / 128, FDIM / 128, NEXP), 512, 147456>>>(x, wg, wu);
    down_mma_kernel<<<dim3(CAP / 128, DDIM / 256, NEXP), 512, 147456>>>(wd);

    combine_kernel<<<(NTOK * 256) / 256, 256>>>(out);
}

// round 7
// speedup vs baseline: 1.1740x; 1.1740x over previous
#include <cuda_runtime.h>
#include <math.h>
#include <stdint.h>

#define NTOK 8192
#define DDIM 1024
#define FDIM 2816
#define NEXP 8
#define CAP  8192

// ---------------- device scratch (referenced ONLY from device code) ----------------
__device__ int   g_count[NEXP];
__device__ int   g_tok[NEXP * CAP];
__device__ int   g_slot[NTOK * 2];
__device__ float g_wt[NTOK * 2];
__device__ float g_xr[(size_t)NTOK * DDIM];              // tf32-rounded X
__device__ float g_wgr[(size_t)NEXP * DDIM * FDIM];      // tf32-rounded weights
__device__ float g_wur[(size_t)NEXP * DDIM * FDIM];
__device__ float g_wdr[(size_t)NEXP * FDIM * DDIM];
__device__ float g_act[(size_t)NEXP * CAP * FDIM];       // tf32-rounded activations
__device__ float g_y[(size_t)NEXP * CAP * DDIM];

// ---------------- helpers ----------------
__device__ __forceinline__ float rn_tf32(float x) {
    float r; asm("cvt.rna.tf32.f32 %0, %1;" : "=f"(r) : "f"(x)); return r;
}
__device__ __forceinline__ uint32_t smem_u32(const void* p) {
    uint32_t a;
    asm("{ .reg .u64 t; cvta.to.shared.u64 t, %1; cvt.u32.u64 %0, t; }" : "=r"(a) : "l"(p));
    return a;
}

#define CPA(dst, src, n) asm volatile("cp.async.cg.shared.global [%0], [%1], 16, %2;" :: "r"(dst), "l"(src), "r"(n) : "memory")
#define CPA_COMMIT()     asm volatile("cp.async.commit_group;" ::: "memory")
#define CPA_WAIT1()      asm volatile("cp.async.wait_group 1;" ::: "memory")

#define MMA_TF32(d, a, b) \
    asm volatile("mma.sync.aligned.m16n8k8.row.col.f32.tf32.tf32.f32 " \
        "{%0,%1,%2,%3}, {%4,%5,%6,%7}, {%8,%9}, {%0,%1,%2,%3};" \
        : "+f"((d)[0]), "+f"((d)[1]), "+f"((d)[2]), "+f"((d)[3]) \
        : "r"((a)[0]), "r"((a)[1]), "r"((a)[2]), "r"((a)[3]), "r"((b)[0]), "r"((b)[1]))

// ---------------- kernel 0: reset ----------------
__global__ void reset_kernel() {
    if (threadIdx.x < NEXP) g_count[threadIdx.x] = 0;
}

// ---------------- kernel 1: router ----------------
__global__ void router_kernel(const float* __restrict__ X, const float* __restrict__ RW) {
    __shared__ float sW[NEXP * DDIM];
    const int tid = threadIdx.x;
    for (int i = tid; i < NEXP * DDIM; i += 128) {
        int d = i >> 3, e = i & 7;
        sW[e * DDIM + d] = RW[i];
    }
    __syncthreads();
    const int warp = tid >> 5, lane = tid & 31;
    const int t = blockIdx.x * 4 + warp;
    const float* xr = X + (size_t)t * DDIM;
    float acc[NEXP];
#pragma unroll
    for (int e = 0; e < NEXP; e++) acc[e] = 0.f;
    for (int d = lane; d < DDIM; d += 32) {
        float xv = xr[d];
#pragma unroll
        for (int e = 0; e < NEXP; e++) acc[e] += xv * sW[e * DDIM + d];
    }
#pragma unroll
    for (int e = 0; e < NEXP; e++)
#pragma unroll
        for (int off = 16; off > 0; off >>= 1)
            acc[e] += __shfl_xor_sync(0xFFFFFFFFu, acc[e], off);
    if (lane == 0) {
        int i0 = 0; float s0 = acc[0];
#pragma unroll
        for (int e = 1; e < NEXP; e++) if (acc[e] > s0) { s0 = acc[e]; i0 = e; }
        int i1 = -1; float s1 = -INFINITY;
#pragma unroll
        for (int e = 0; e < NEXP; e++) if (e != i0 && acc[e] > s1) { s1 = acc[e]; i1 = e; }
        float w0 = 1.f / (1.f + expf(s1 - s0));
        float w1 = 1.f - w0;
        int p0 = atomicAdd(&g_count[i0], 1);
        int p1 = atomicAdd(&g_count[i1], 1);
        g_tok[i0 * CAP + p0] = t;
        g_tok[i1 * CAP + p1] = t;
        g_slot[2 * t + 0] = i0 * CAP + p0;  g_wt[2 * t + 0] = w0;
        g_slot[2 * t + 1] = i1 * CAP + p1;  g_wt[2 * t + 1] = w1;
    }
}

// ---------------- kernel 1b: round X -> g_xr (device symbol referenced in-kernel) ----------------
__global__ void roundx_kernel(const float* __restrict__ X) {
    size_t i = (size_t)blockIdx.x * 256 + threadIdx.x;
    float4 v = ((const float4*)X)[i];
    v.x = rn_tf32(v.x); v.y = rn_tf32(v.y); v.z = rn_tf32(v.z); v.w = rn_tf32(v.w);
    ((float4*)g_xr)[i] = v;
}

// ---------------- kernel 1c: round weights -> g_wgr/g_wur/g_wdr ----------------
__global__ void roundw_kernel(const float* __restrict__ Wg,
                              const float* __restrict__ Wu,
                              const float* __restrict__ Wd) {
    size_t i = (size_t)blockIdx.x * 256 + threadIdx.x;
    float4 a = ((const float4*)Wg)[i];
    a.x = rn_tf32(a.x); a.y = rn_tf32(a.y); a.z = rn_tf32(a.z); a.w = rn_tf32(a.w);
    ((float4*)g_wgr)[i] = a;
    float4 b = ((const float4*)Wu)[i];
    b.x = rn_tf32(b.x); b.y = rn_tf32(b.y); b.z = rn_tf32(b.z); b.w = rn_tf32(b.w);
    ((float4*)g_wur)[i] = b;
    float4 c = ((const float4*)Wd)[i];
    c.x = rn_tf32(c.x); c.y = rn_tf32(c.y); c.z = rn_tf32(c.z); c.w = rn_tf32(c.w);
    ((float4*)g_wdr)[i] = c;
}

// ================= tf32 mma.sync GEMMs =================
// CTA tile 128x128x32, 8 warps (2M x 4N), warp tile 64x32, mma m16n8k8.
// A smem [m][k] 128x32, chunk swizzle c^=(r&7).  B smem [k][n] 32x128, chunk swizzle c^=2*(k&3).
// All operands pre-rounded to tf32 in gmem -> raw bit loads, no cvt in loop.

__device__ __forceinline__ void load_frag_a(
    const float* A, int k8, int wm, int lr, int lc, uint32_t fa[4][4]) {
#pragma unroll
    for (int mi = 0; mi < 4; mi++) {
        const int r0 = wm * 64 + mi * 16 + lr;
#pragma unroll
        for (int h = 0; h < 2; h++) {
            const int cx = (((2 * k8 + h) ^ lr) << 2) + lc;
            fa[mi][h * 2 + 0] = __float_as_uint(A[r0 * 32 + cx]);
            fa[mi][h * 2 + 1] = __float_as_uint(A[(r0 + 8) * 32 + cx]);
        }
    }
}
__device__ __forceinline__ void load_frag_b(
    const float* B, int k8, int wn, int lr, int lc, uint32_t fb[4][2]) {
#pragma unroll
    for (int ni = 0; ni < 4; ni++) {
        const int c = wn * 8 + ni * 2 + (lr >> 2);
        const int bx = ((c ^ (lc << 1)) << 2) + (lr & 3);
#pragma unroll
        for (int h = 0; h < 2; h++)
            fb[ni][h] = __float_as_uint(B[(k8 * 8 + lc + 4 * h) * 128 + bx]);
    }
}

// ---------------- kernel 2: fused gate+up + SiLU ----------------
__global__ void __launch_bounds__(256, 1)
gateup_mma_kernel() {
    extern __shared__ float smem[];
    float* As  = smem;              // 3 * 4096
    float* Bgs = smem + 12288;
    float* Bus = smem + 24576;

    const int e = blockIdx.z;
    const int cnt = g_count[e];
    const int m0 = blockIdx.x * 128;
    if (m0 >= cnt) return;
    const int n0 = blockIdx.y * 128;

    const int tid = threadIdx.x, wid = tid >> 5, lane = tid & 31;
    const int wm = wid & 1, wn = wid >> 1;
    const int lr = lane >> 2, lc = lane & 3;

    const int ar = tid >> 1;
    const bool av = (m0 + ar) < cnt;
    const float* arow = g_xr + (size_t)(av ? g_tok[e * CAP + m0 + ar] : 0) * DDIM;
    const int an = av ? 16 : 0;
    uint32_t aoff[4]; int ac[4];
#pragma unroll
    for (int i = 0; i < 4; i++) {
        int c = (tid & 1) * 4 + i;
        ac[i] = c;
        aoff[i] = (uint32_t)(ar * 128 + ((c ^ (ar & 7)) << 4));
    }
    const int bk = tid >> 3;
    const float* grow = g_wgr + ((size_t)e * DDIM + bk) * FDIM + n0;
    const float* urow = g_wur + ((size_t)e * DDIM + bk) * FDIM + n0;
    uint32_t boff[4]; int bc[4];
#pragma unroll
    for (int i = 0; i < 4; i++) {
        int c = (tid & 7) + 8 * i;
        bc[i] = c;
        boff[i] = (uint32_t)(bk * 512 + ((c ^ ((bk & 3) << 1)) << 4));
    }

    const uint32_t sA = smem_u32(As), sG = smem_u32(Bgs), sU = smem_u32(Bus);

    float accg[4][4][4], accu[4][4][4];
#pragma unroll
    for (int mi = 0; mi < 4; mi++)
#pragma unroll
        for (int ni = 0; ni < 4; ni++)
#pragma unroll
            for (int q = 0; q < 4; q++) { accg[mi][ni][q] = 0.f; accu[mi][ni][q] = 0.f; }

    const int KT = DDIM / 32;   // 32

#define GU_PREFETCH(s) do { \
    int _buf = (s) % 3; \
    uint32_t _da = sA + _buf * 16384, _dg = sG + _buf * 16384, _du = sU + _buf * 16384; \
    const float* _ap = arow + (s) * 32; \
    const float* _gp = grow + (size_t)(s) * 32 * FDIM; \
    const float* _up = urow + (size_t)(s) * 32 * FDIM; \
    _Pragma("unroll") \
    for (int _i = 0; _i < 4; _i++) { \
        CPA(_da + aoff[_i], _ap + ac[_i] * 4, an); \
        CPA(_dg + boff[_i], _gp + bc[_i] * 4, 16); \
        CPA(_du + boff[_i], _up + bc[_i] * 4, 16); \
    } } while (0)

    GU_PREFETCH(0); CPA_COMMIT();
    GU_PREFETCH(1); CPA_COMMIT();
    CPA_WAIT1();
    __syncthreads();

    uint32_t fa[2][4][4], fg[2][4][2], fu[2][4][2];
    load_frag_a(As, 0, wm, lr, lc, fa[0]);
    load_frag_b(Bgs, 0, wn, lr, lc, fg[0]);
    load_frag_b(Bus, 0, wn, lr, lc, fu[0]);

    for (int s = 0; s < KT; s++) {
        const int buf = s % 3;
        const float* A = As  + buf * 4096;
        const float* G = Bgs + buf * 4096;
        const float* U = Bus + buf * 4096;
#pragma unroll
        for (int k8 = 0; k8 < 4; k8++) {
            const int cur = k8 & 1, nxt = (k8 + 1) & 1;
            if (k8 < 3) {
                load_frag_a(A, k8 + 1, wm, lr, lc, fa[nxt]);
                load_frag_b(G, k8 + 1, wn, lr, lc, fg[nxt]);
                load_frag_b(U, k8 + 1, wn, lr, lc, fu[nxt]);
            }
#pragma unroll
            for (int ni = 0; ni < 4; ni++)
#pragma unroll
                for (int mi = 0; mi < 4; mi++) {
                    MMA_TF32(accg[mi][ni], fa[cur][mi], fg[cur][ni]);
                    MMA_TF32(accu[mi][ni], fa[cur][mi], fu[cur][ni]);
                }
        }
        if (s + 1 < KT) {
            if (s + 2 < KT) { GU_PREFETCH(s + 2); }
            CPA_COMMIT();
            CPA_WAIT1();
            __syncthreads();
            const int nb = (s + 1) % 3;
            load_frag_a(As + nb * 4096, 0, wm, lr, lc, fa[0]);
            load_frag_b(Bgs + nb * 4096, 0, wn, lr, lc, fg[0]);
            load_frag_b(Bus + nb * 4096, 0, wn, lr, lc, fu[0]);
        }
    }

    // epilogue: act = rn_tf32(silu(g)*u)
#pragma unroll
    for (int mi = 0; mi < 4; mi++) {
        const int r = wm * 64 + mi * 16 + lr;
        const size_t row0 = (size_t)e * CAP + m0 + r;
#pragma unroll
        for (int ni = 0; ni < 4; ni++) {
            const int col = n0 + wn * 32 + ni * 8 + 2 * lc;
            if (m0 + r < cnt) {
                float g0 = accg[mi][ni][0], g1 = accg[mi][ni][1];
                float2 v;
                v.x = rn_tf32((g0 / (1.f + __expf(-g0))) * accu[mi][ni][0]);
                v.y = rn_tf32((g1 / (1.f + __expf(-g1))) * accu[mi][ni][1]);
                *(float2*)&g_act[row0 * FDIM + col] = v;
            }
            if (m0 + r + 8 < cnt) {
                float g2 = accg[mi][ni][2], g3 = accg[mi][ni][3];
                float2 v;
                v.x = rn_tf32((g2 / (1.f + __expf(-g2))) * accu[mi][ni][2]);
                v.y = rn_tf32((g3 / (1.f + __expf(-g3))) * accu[mi][ni][3]);
                *(float2*)&g_act[(row0 + 8) * FDIM + col] = v;
            }
        }
    }
}

// ---------------- kernel 3: down GEMM ----------------
__global__ void __launch_bounds__(256, 1)
down_mma_kernel() {
    extern __shared__ float smem[];
    float* As = smem;               // 3 * 4096
    float* Bs = smem + 12288;       // 3 * 4096

    const int e = blockIdx.z;
    const int cnt = g_count[e];
    const int m0 = blockIdx.x * 128;
    if (m0 >= cnt) return;
    const int n0 = blockIdx.y * 128;

    const int tid = threadIdx.x, wid = tid >> 5, lane = tid & 31;
    const int wm = wid & 1, wn = wid >> 1;
    const int lr = lane >> 2, lc = lane & 3;

    const int ar = tid >> 1;
    const bool av = (m0 + ar) < cnt;
    const float* arow = g_act + ((size_t)e * CAP + m0 + (av ? ar : 0)) * FDIM;
    const int an = av ? 16 : 0;
    uint32_t aoff[4]; int ac[4];
#pragma unroll
    for (int i = 0; i < 4; i++) {
        int c = (tid & 1) * 4 + i;
        ac[i] = c;
        aoff[i] = (uint32_t)(ar * 128 + ((c ^ (ar & 7)) << 4));
    }
    const int bk = tid >> 3;
    const float* brow = g_wdr + ((size_t)e * FDIM + bk) * DDIM + n0;
    uint32_t boff[4]; int bc[4];
#pragma unroll
    for (int i = 0; i < 4; i++) {
        int c = (tid & 7) + 8 * i;
        bc[i] = c;
        boff[i] = (uint32_t)(bk * 512 + ((c ^ ((bk & 3) << 1)) << 4));
    }

    const uint32_t sA = smem_u32(As), sB = smem_u32(Bs);

    float acc[4][4][4];
#pragma unroll
    for (int mi = 0; mi < 4; mi++)
#pragma unroll
        for (int ni = 0; ni < 4; ni++)
#pragma unroll
            for (int q = 0; q < 4; q++) acc[mi][ni][q] = 0.f;

    const int KT = FDIM / 32;   // 88

#define DN_PREFETCH(s) do { \
    int _buf = (s) % 3; \
    uint32_t _da = sA + _buf * 16384, _db = sB + _buf * 16384; \
    const float* _ap = arow + (s) * 32; \
    const float* _bp = brow + (size_t)(s) * 32 * DDIM; \
    _Pragma("unroll") \
    for (int _i = 0; _i < 4; _i++) { \
        CPA(_da + aoff[_i], _ap + ac[_i] * 4, an); \
        CPA(_db + boff[_i], _bp + bc[_i] * 4, 16); \
    } } while (0)

    DN_PREFETCH(0); CPA_COMMIT();
    DN_PREFETCH(1); CPA_COMMIT();
    CPA_WAIT1();
    __syncthreads();

    uint32_t fa[2][4][4], fb[2][4][2];
    load_frag_a(As, 0, wm, lr, lc, fa[0]);
    load_frag_b(Bs, 0, wn, lr, lc, fb[0]);

    for (int s = 0; s < KT; s++) {
        const int buf = s % 3;
        const float* A = As + buf * 4096;
        const float* B = Bs + buf * 4096;
#pragma unroll
        for (int k8 = 0; k8 < 4; k8++) {
            const int cur = k8 & 1, nxt = (k8 + 1) & 1;
            if (k8 < 3) {
                load_frag_a(A, k8 + 1, wm, lr, lc, fa[nxt]);
                load_frag_b(B, k8 + 1, wn, lr, lc, fb[nxt]);
            }
#pragma unroll
            for (int ni = 0; ni < 4; ni++)
#pragma unroll
                for (int mi = 0; mi < 4; mi++)
                    MMA_TF32(acc[mi][ni], fa[cur][mi], fb[cur][ni]);
        }
        if (s + 1 < KT) {
            if (s + 2 < KT) { DN_PREFETCH(s + 2); }
            CPA_COMMIT();
            CPA_WAIT1();
            __syncthreads();
            const int nb = (s + 1) % 3;
            load_frag_a(As + nb * 4096, 0, wm, lr, lc, fa[0]);
            load_frag_b(Bs + nb * 4096, 0, wn, lr, lc, fb[0]);
        }
    }

#pragma unroll
    for (int mi = 0; mi < 4; mi++) {
        const int r = wm * 64 + mi * 16 + lr;
        const size_t row0 = (size_t)e * CAP + m0 + r;
#pragma unroll
        for (int ni = 0; ni < 4; ni++) {
            const int col = n0 + wn * 32 + ni * 8 + 2 * lc;
            if (m0 + r < cnt) {
                float2 v; v.x = acc[mi][ni][0]; v.y = acc[mi][ni][1];
                *(float2*)&g_y[row0 * DDIM + col] = v;
            }
            if (m0 + r + 8 < cnt) {
                float2 v; v.x = acc[mi][ni][2]; v.y = acc[mi][ni][3];
                *(float2*)&g_y[(row0 + 8) * DDIM + col] = v;
            }
        }
    }
}

// ---------------- kernel 4: weighted combine ----------------
__global__ void combine_kernel(float* __restrict__ out) {
    const int g = blockIdx.x * blockDim.x + threadIdx.x;
    const int t = g >> 8;
    const int c = g & 255;
    const int s0 = g_slot[2 * t], s1 = g_slot[2 * t + 1];
    const float w0 = g_wt[2 * t], w1 = g_wt[2 * t + 1];
    const float4* Y = (const float4*)g_y;
    float4 a = Y[(size_t)s0 * 256 + c];
    float4 b = Y[(size_t)s1 * 256 + c];
    float4 o;
    o.x = w0 * a.x + w1 * b.x;
    o.y = w0 * a.y + w1 * b.y;
    o.z = w0 * a.z + w1 * b.z;
    o.w = w0 * a.w + w1 * b.w;
    ((float4*)out)[g] = o;
}

// ---------------- launch ----------------
extern "C" void kernel_launch(void* const* d_in, const int* in_sizes, int n_in,
                              void* d_out, int out_size) {
    const float* x  = (const float*)d_in[0];
    const float* rw = (const float*)d_in[1];
    const float* wg = (const float*)d_in[2];
    const float* wu = (const float*)d_in[3];
    const float* wd = (const float*)d_in[4];
    float* out = (float*)d_out;

    cudaFuncSetAttribute(gateup_mma_kernel, cudaFuncAttributeMaxDynamicSharedMemorySize, 147456);
    cudaFuncSetAttribute(down_mma_kernel,   cudaFuncAttributeMaxDynamicSharedMemorySize, 98304);

    reset_kernel<<<1, 32>>>();
    router_kernel<<<NTOK / 4, 128>>>(x, rw);

    // pre-round operands to tf32 (device globals written INSIDE kernels, not via host args)
    roundx_kernel<<<(NTOK * DDIM / 4) / 256, 256>>>(x);
    roundw_kernel<<<(NEXP * DDIM * FDIM / 4) / 256, 256>>>(wg, wu, wd);

    gateup_mma_kernel<<<dim3(CAP / 128, FDIM / 128, NEXP), 256, 147456>>>();
    down_mma_kernel<<<dim3(CAP / 128, DDIM / 128, NEXP), 256, 98304>>>();

    combine_kernel<<<(NTOK * 256) / 256, 256>>>(out);
}

// round 8
// speedup vs baseline: 1.1924x; 1.0157x over previous
#include <cuda_runtime.h>
#include <math.h>
#include <stdint.h>

#define NTOK 8192
#define DDIM 1024
#define FDIM 2816
#define NEXP 8
#define CAP  8192

// ---------------- device scratch (referenced ONLY from device code) ----------------
__device__ int   g_count[NEXP];
__device__ int   g_tok[NEXP * CAP];
__device__ int   g_slot[NTOK * 2];
__device__ float g_wt[NTOK * 2];
__device__ float g_xr[(size_t)NTOK * DDIM];
__device__ float g_wgr[(size_t)NEXP * DDIM * FDIM];
__device__ float g_wur[(size_t)NEXP * DDIM * FDIM];
__device__ float g_wdr[(size_t)NEXP * FDIM * DDIM];
__device__ float g_act[(size_t)NEXP * CAP * FDIM];
__device__ float g_y[(size_t)NEXP * CAP * DDIM];

// ---------------- helpers ----------------
__device__ __forceinline__ float rn_tf32(float x) {
    float r; asm("cvt.rna.tf32.f32 %0, %1;" : "=f"(r) : "f"(x)); return r;
}
__device__ __forceinline__ uint32_t smem_u32(const void* p) {
    uint32_t a;
    asm("{ .reg .u64 t; cvta.to.shared.u64 t, %1; cvt.u32.u64 %0, t; }" : "=r"(a) : "l"(p));
    return a;
}

#define CPA(dst, src, n) asm volatile("cp.async.cg.shared.global [%0], [%1], 16, %2;" :: "r"(dst), "l"(src), "r"(n) : "memory")
#define CPA_COMMIT()     asm volatile("cp.async.commit_group;" ::: "memory")
#define CPA_WAIT0()      asm volatile("cp.async.wait_group 0;" ::: "memory")
#define CPA_WAIT2()      asm volatile("cp.async.wait_group 2;" ::: "memory")

#define MMA_TF32(d, a, b) \
    asm volatile("mma.sync.aligned.m16n8k8.row.col.f32.tf32.tf32.f32 " \
        "{%0,%1,%2,%3}, {%4,%5,%6,%7}, {%8,%9}, {%0,%1,%2,%3};" \
        : "+f"((d)[0]), "+f"((d)[1]), "+f"((d)[2]), "+f"((d)[3]) \
        : "r"((a)[0]), "r"((a)[1]), "r"((a)[2]), "r"((a)[3]), "r"((b)[0]), "r"((b)[1]))

// ---------------- kernel 0: reset ----------------
__global__ void reset_kernel() {
    if (threadIdx.x < NEXP) g_count[threadIdx.x] = 0;
}

// ---------------- kernel 1: router ----------------
__global__ void router_kernel(const float* __restrict__ X, const float* __restrict__ RW) {
    __shared__ float sW[NEXP * DDIM];
    const int tid = threadIdx.x;
    for (int i = tid; i < NEXP * DDIM; i += 128) {
        int d = i >> 3, e = i & 7;
        sW[e * DDIM + d] = RW[i];
    }
    __syncthreads();
    const int warp = tid >> 5, lane = tid & 31;
    const int t = blockIdx.x * 4 + warp;
    const float* xr = X + (size_t)t * DDIM;
    float acc[NEXP];
#pragma unroll
    for (int e = 0; e < NEXP; e++) acc[e] = 0.f;
    for (int d = lane; d < DDIM; d += 32) {
        float xv = xr[d];
#pragma unroll
        for (int e = 0; e < NEXP; e++) acc[e] += xv * sW[e * DDIM + d];
    }
#pragma unroll
    for (int e = 0; e < NEXP; e++)
#pragma unroll
        for (int off = 16; off > 0; off >>= 1)
            acc[e] += __shfl_xor_sync(0xFFFFFFFFu, acc[e], off);
    if (lane == 0) {
        int i0 = 0; float s0 = acc[0];
#pragma unroll
        for (int e = 1; e < NEXP; e++) if (acc[e] > s0) { s0 = acc[e]; i0 = e; }
        int i1 = -1; float s1 = -INFINITY;
#pragma unroll
        for (int e = 0; e < NEXP; e++) if (e != i0 && acc[e] > s1) { s1 = acc[e]; i1 = e; }
        float w0 = 1.f / (1.f + expf(s1 - s0));
        float w1 = 1.f - w0;
        int p0 = atomicAdd(&g_count[i0], 1);
        int p1 = atomicAdd(&g_count[i1], 1);
        g_tok[i0 * CAP + p0] = t;
        g_tok[i1 * CAP + p1] = t;
        g_slot[2 * t + 0] = i0 * CAP + p0;  g_wt[2 * t + 0] = w0;
        g_slot[2 * t + 1] = i1 * CAP + p1;  g_wt[2 * t + 1] = w1;
    }
}

// ---------------- kernel 1b/1c: round to tf32 ----------------
__global__ void roundx_kernel(const float* __restrict__ X) {
    size_t i = (size_t)blockIdx.x * 256 + threadIdx.x;
    float4 v = ((const float4*)X)[i];
    v.x = rn_tf32(v.x); v.y = rn_tf32(v.y); v.z = rn_tf32(v.z); v.w = rn_tf32(v.w);
    ((float4*)g_xr)[i] = v;
}
__global__ void roundw_kernel(const float* __restrict__ Wg,
                              const float* __restrict__ Wu,
                              const float* __restrict__ Wd) {
    size_t i = (size_t)blockIdx.x * 256 + threadIdx.x;
    float4 a = ((const float4*)Wg)[i];
    a.x = rn_tf32(a.x); a.y = rn_tf32(a.y); a.z = rn_tf32(a.z); a.w = rn_tf32(a.w);
    ((float4*)g_wgr)[i] = a;
    float4 b = ((const float4*)Wu)[i];
    b.x = rn_tf32(b.x); b.y = rn_tf32(b.y); b.z = rn_tf32(b.z); b.w = rn_tf32(b.w);
    ((float4*)g_wur)[i] = b;
    float4 c = ((const float4*)Wd)[i];
    c.x = rn_tf32(c.x); c.y = rn_tf32(c.y); c.z = rn_tf32(c.z); c.w = rn_tf32(c.w);
    ((float4*)g_wdr)[i] = c;
}

// ================= tf32 mma.sync GEMMs, CTA 64x128x32, 2 CTAs/SM =================
// 8 warps (2M x 4N), warp tile 32x32. A smem [m][k] 64x32 (row 128B, chunk ^ r&7).
// B smem [k][n] 32x128 (row 512B, chunk ^ 2*(k&3)). Pre-rounded operands, no cvt.

__device__ __forceinline__ void load_frag_a2(
    const float* A, int k8, int wm, int lr, int lc, uint32_t fa[2][4]) {
#pragma unroll
    for (int mi = 0; mi < 2; mi++) {
        const int r0 = wm * 32 + mi * 16 + lr;
#pragma unroll
        for (int h = 0; h < 2; h++) {
            const int cx = (((2 * k8 + h) ^ lr) << 2) + lc;
            fa[mi][h * 2 + 0] = __float_as_uint(A[r0 * 32 + cx]);
            fa[mi][h * 2 + 1] = __float_as_uint(A[(r0 + 8) * 32 + cx]);
        }
    }
}
__device__ __forceinline__ void load_frag_b4(
    const float* B, int k8, int wn, int lr, int lc, uint32_t fb[4][2]) {
#pragma unroll
    for (int ni = 0; ni < 4; ni++) {
        const int c = wn * 8 + ni * 2 + (lr >> 2);
        const int bx = ((c ^ (lc << 1)) << 2) + (lr & 3);
#pragma unroll
        for (int h = 0; h < 2; h++)
            fb[ni][h] = __float_as_uint(B[(k8 * 8 + lc + 4 * h) * 128 + bx]);
    }
}

// ---------------- kernel 2: fused gate+up + SiLU (2-stage, 80KB) ----------------
__global__ void __launch_bounds__(256, 2)
gateup_mma_kernel() {
    extern __shared__ float smem[];
    float* As  = smem;              // 2 stages x 2048 floats
    float* Bgs = smem + 4096;       // 2 stages x 4096
    float* Bus = smem + 12288;      // 2 stages x 4096

    const int e = blockIdx.z;
    const int cnt = g_count[e];
    const int m0 = blockIdx.x * 64;
    if (m0 >= cnt) return;
    const int n0 = blockIdx.y * 128;

    const int tid = threadIdx.x, wid = tid >> 5, lane = tid & 31;
    const int wm = wid & 1, wn = wid >> 1;
    const int lr = lane >> 2, lc = lane & 3;

    // A gmem->smem: row = tid>>2 (0..63), 2 chunks of 16B
    const int ar = tid >> 2;
    const bool av = (m0 + ar) < cnt;
    const float* arow = g_xr + (size_t)(av ? g_tok[e * CAP + m0 + ar] : 0) * DDIM;
    const int an = av ? 16 : 0;
    uint32_t aoff[2]; int ac[2];
#pragma unroll
    for (int i = 0; i < 2; i++) {
        int c = (tid & 3) + 4 * i;
        ac[i] = c;
        aoff[i] = (uint32_t)(ar * 128 + ((c ^ (ar & 7)) << 4));
    }
    // B gmem->smem: k-row = tid>>3 (0..31), 4 chunks each of G,U
    const int bk = tid >> 3;
    const float* grow = g_wgr + ((size_t)e * DDIM + bk) * FDIM + n0;
    const float* urow = g_wur + ((size_t)e * DDIM + bk) * FDIM + n0;
    uint32_t boff[4]; int bc[4];
#pragma unroll
    for (int i = 0; i < 4; i++) {
        int c = (tid & 7) + 8 * i;
        bc[i] = c;
        boff[i] = (uint32_t)(bk * 512 + ((c ^ ((bk & 3) << 1)) << 4));
    }

    const uint32_t sA = smem_u32(As), sG = smem_u32(Bgs), sU = smem_u32(Bus);

    float accg[2][4][4], accu[2][4][4];
#pragma unroll
    for (int mi = 0; mi < 2; mi++)
#pragma unroll
        for (int ni = 0; ni < 4; ni++)
#pragma unroll
            for (int q = 0; q < 4; q++) { accg[mi][ni][q] = 0.f; accu[mi][ni][q] = 0.f; }

    const int KT = DDIM / 32;   // 32

#define GU_PREFETCH(s) do { \
    int _buf = (s) & 1; \
    uint32_t _da = sA + _buf * 8192, _dg = sG + _buf * 16384, _du = sU + _buf * 16384; \
    const float* _ap = arow + (s) * 32; \
    const float* _gp = grow + (size_t)(s) * 32 * FDIM; \
    const float* _up = urow + (size_t)(s) * 32 * FDIM; \
    _Pragma("unroll") \
    for (int _i = 0; _i < 2; _i++) CPA(_da + aoff[_i], _ap + ac[_i] * 4, an); \
    _Pragma("unroll") \
    for (int _i = 0; _i < 4; _i++) { \
        CPA(_dg + boff[_i], _gp + bc[_i] * 4, 16); \
        CPA(_du + boff[_i], _up + bc[_i] * 4, 16); \
    } } while (0)

    GU_PREFETCH(0); CPA_COMMIT();

    for (int s = 0; s < KT; s++) {
        CPA_WAIT0();
        __syncthreads();
        if (s + 1 < KT) { GU_PREFETCH(s + 1); }
        CPA_COMMIT();
        const int buf = s & 1;
        const float* A = As  + buf * 2048;
        const float* G = Bgs + buf * 4096;
        const float* U = Bus + buf * 4096;
        uint32_t fa[2][2][4], fg[2][4][2], fu[2][4][2];
        load_frag_a2(A, 0, wm, lr, lc, fa[0]);
        load_frag_b4(G, 0, wn, lr, lc, fg[0]);
        load_frag_b4(U, 0, wn, lr, lc, fu[0]);
#pragma unroll
        for (int k8 = 0; k8 < 4; k8++) {
            const int cur = k8 & 1, nxt = (k8 + 1) & 1;
            if (k8 < 3) {
                load_frag_a2(A, k8 + 1, wm, lr, lc, fa[nxt]);
                load_frag_b4(G, k8 + 1, wn, lr, lc, fg[nxt]);
                load_frag_b4(U, k8 + 1, wn, lr, lc, fu[nxt]);
            }
#pragma unroll
            for (int ni = 0; ni < 4; ni++)
#pragma unroll
                for (int mi = 0; mi < 2; mi++) {
                    MMA_TF32(accg[mi][ni], fa[cur][mi], fg[cur][ni]);
                    MMA_TF32(accu[mi][ni], fa[cur][mi], fu[cur][ni]);
                }
        }
        __syncthreads();   // stage consumed; safe for next prefetch overwrite
    }

    // epilogue: act = rn_tf32(silu(g)*u)
#pragma unroll
    for (int mi = 0; mi < 2; mi++) {
        const int r = wm * 32 + mi * 16 + lr;
        const size_t row0 = (size_t)e * CAP + m0 + r;
#pragma unroll
        for (int ni = 0; ni < 4; ni++) {
            const int col = n0 + wn * 32 + ni * 8 + 2 * lc;
            if (m0 + r < cnt) {
                float g0 = accg[mi][ni][0], g1 = accg[mi][ni][1];
                float2 v;
                v.x = rn_tf32((g0 / (1.f + __expf(-g0))) * accu[mi][ni][0]);
                v.y = rn_tf32((g1 / (1.f + __expf(-g1))) * accu[mi][ni][1]);
                *(float2*)&g_act[row0 * FDIM + col] = v;
            }
            if (m0 + r + 8 < cnt) {
                float g2 = accg[mi][ni][2], g3 = accg[mi][ni][3];
                float2 v;
                v.x = rn_tf32((g2 / (1.f + __expf(-g2))) * accu[mi][ni][2]);
                v.y = rn_tf32((g3 / (1.f + __expf(-g3))) * accu[mi][ni][3]);
                *(float2*)&g_act[(row0 + 8) * FDIM + col] = v;
            }
        }
    }
}

// ---------------- kernel 3: down GEMM (4-stage, 96KB) ----------------
__global__ void __launch_bounds__(256, 2)
down_mma_kernel() {
    extern __shared__ float smem[];
    float* As = smem;               // 4 stages x 2048 floats
    float* Bs = smem + 8192;        // 4 stages x 4096 floats

    const int e = blockIdx.z;
    const int cnt = g_count[e];
    const int m0 = blockIdx.x * 64;
    if (m0 >= cnt) return;
    const int n0 = blockIdx.y * 128;

    const int tid = threadIdx.x, wid = tid >> 5, lane = tid & 31;
    const int wm = wid & 1, wn = wid >> 1;
    const int lr = lane >> 2, lc = lane & 3;

    const int ar = tid >> 2;
    const bool av = (m0 + ar) < cnt;
    const float* arow = g_act + ((size_t)e * CAP + m0 + (av ? ar : 0)) * FDIM;
    const int an = av ? 16 : 0;
    uint32_t aoff[2]; int ac[2];
#pragma unroll
    for (int i = 0; i < 2; i++) {
        int c = (tid & 3) + 4 * i;
        ac[i] = c;
        aoff[i] = (uint32_t)(ar * 128 + ((c ^ (ar & 7)) << 4));
    }
    const int bk = tid >> 3;
    const float* brow = g_wdr + ((size_t)e * FDIM + bk) * DDIM + n0;
    uint32_t boff[4]; int bc[4];
#pragma unroll
    for (int i = 0; i < 4; i++) {
        int c = (tid & 7) + 8 * i;
        bc[i] = c;
        boff[i] = (uint32_t)(bk * 512 + ((c ^ ((bk & 3) << 1)) << 4));
    }

    const uint32_t sA = smem_u32(As), sB = smem_u32(Bs);

    float acc[2][4][4];
#pragma unroll
    for (int mi = 0; mi < 2; mi++)
#pragma unroll
        for (int ni = 0; ni < 4; ni++)
#pragma unroll
            for (int q = 0; q < 4; q++) acc[mi][ni][q] = 0.f;

    const int KT = FDIM / 32;   // 88

#define DN_PREFETCH(s) do { \
    int _buf = (s) & 3; \
    uint32_t _da = sA + _buf * 8192, _db = sB + _buf * 16384; \
    const float* _ap = arow + (s) * 32; \
    const float* _bp = brow + (size_t)(s) * 32 * DDIM; \
    _Pragma("unroll") \
    for (int _i = 0; _i < 2; _i++) CPA(_da + aoff[_i], _ap + ac[_i] * 4, an); \
    _Pragma("unroll") \
    for (int _i = 0; _i < 4; _i++) CPA(_db + boff[_i], _bp + bc[_i] * 4, 16); \
    } while (0)

    DN_PREFETCH(0); CPA_COMMIT();
    DN_PREFETCH(1); CPA_COMMIT();
    DN_PREFETCH(2); CPA_COMMIT();

    for (int s = 0; s < KT; s++) {
        CPA_WAIT2();
        __syncthreads();
        if (s + 3 < KT) { DN_PREFETCH(s + 3); }
        CPA_COMMIT();
        const int buf = s & 3;
        const float* A = As + buf * 2048;
        const float* B = Bs + buf * 4096;
        uint32_t fa[2][2][4], fb[2][4][2];
        load_frag_a2(A, 0, wm, lr, lc, fa[0]);
        load_frag_b4(B, 0, wn, lr, lc, fb[0]);
#pragma unroll
        for (int k8 = 0; k8 < 4; k8++) {
            const int cur = k8 & 1, nxt = (k8 + 1) & 1;
            if (k8 < 3) {
                load_frag_a2(A, k8 + 1, wm, lr, lc, fa[nxt]);
                load_frag_b4(B, k8 + 1, wn, lr, lc, fb[nxt]);
            }
#pragma unroll
            for (int ni = 0; ni < 4; ni++)
#pragma unroll
                for (int mi = 0; mi < 2; mi++)
                    MMA_TF32(acc[mi][ni], fa[cur][mi], fb[cur][ni]);
        }
        __syncthreads();
    }

#pragma unroll
    for (int mi = 0; mi < 2; mi++) {
        const int r = wm * 32 + mi * 16 + lr;
        const size_t row0 = (size_t)e * CAP + m0 + r;
#pragma unroll
        for (int ni = 0; ni < 4; ni++) {
            const int col = n0 + wn * 32 + ni * 8 + 2 * lc;
            if (m0 + r < cnt) {
                float2 v; v.x = acc[mi][ni][0]; v.y = acc[mi][ni][1];
                *(float2*)&g_y[row0 * DDIM + col] = v;
            }
            if (m0 + r + 8 < cnt) {
                float2 v; v.x = acc[mi][ni][2]; v.y = acc[mi][ni][3];
                *(float2*)&g_y[(row0 + 8) * DDIM + col] = v;
            }
        }
    }
}

// ---------------- kernel 4: weighted combine ----------------
__global__ void combine_kernel(float* __restrict__ out) {
    const int g = blockIdx.x * blockDim.x + threadIdx.x;
    const int t = g >> 8;
    const int c = g & 255;
    const int s0 = g_slot[2 * t], s1 = g_slot[2 * t + 1];
    const float w0 = g_wt[2 * t], w1 = g_wt[2 * t + 1];
    const float4* Y = (const float4*)g_y;
    float4 a = Y[(size_t)s0 * 256 + c];
    float4 b = Y[(size_t)s1 * 256 + c];
    float4 o;
    o.x = w0 * a.x + w1 * b.x;
    o.y = w0 * a.y + w1 * b.y;
    o.z = w0 * a.z + w1 * b.z;
    o.w = w0 * a.w + w1 * b.w;
    ((float4*)out)[g] = o;
}

// ---------------- launch ----------------
extern "C" void kernel_launch(void* const* d_in, const int* in_sizes, int n_in,
                              void* d_out, int out_size) {
    const float* x  = (const float*)d_in[0];
    const float* rw = (const float*)d_in[1];
    const float* wg = (const float*)d_in[2];
    const float* wu = (const float*)d_in[3];
    const float* wd = (const float*)d_in[4];
    float* out = (float*)d_out;

    cudaFuncSetAttribute(gateup_mma_kernel, cudaFuncAttributeMaxDynamicSharedMemorySize, 81920);
    cudaFuncSetAttribute(down_mma_kernel,   cudaFuncAttributeMaxDynamicSharedMemorySize, 98304);

    reset_kernel<<<1, 32>>>();
    router_kernel<<<NTOK / 4, 128>>>(x, rw);

    roundx_kernel<<<(NTOK * DDIM / 4) / 256, 256>>>(x);
    roundw_kernel<<<(NEXP * DDIM * FDIM / 4) / 256, 256>>>(wg, wu, wd);

    gateup_mma_kernel<<<dim3(CAP / 64, FDIM / 128, NEXP), 256, 81920>>>();
    down_mma_kernel<<<dim3(CAP / 64, DDIM / 128, NEXP), 256, 98304>>>();

    combine_kernel<<<(NTOK * 256) / 256, 256>>>(out);
}

// round 9
// speedup vs baseline: 1.2633x; 1.0594x over previous
#include <cuda_runtime.h>
#include <math.h>
#include <stdint.h>

#define NTOK 8192
#define DDIM 1024
#define FDIM 2816
#define NEXP 8
#define CAP  8192

// ---------------- device scratch (referenced ONLY from device code) ----------------
__device__ int   g_count[NEXP];
__device__ int   g_tok[NEXP * CAP];
__device__ int   g_slot[NTOK * 2];
__device__ float g_wt[NTOK * 2];
__device__ float g_xr[(size_t)NTOK * DDIM];
__device__ float g_wgr[(size_t)NEXP * DDIM * FDIM];
__device__ float g_wur[(size_t)NEXP * DDIM * FDIM];
__device__ float g_wdr[(size_t)NEXP * FDIM * DDIM];
__device__ float g_act[(size_t)NEXP * CAP * FDIM];
__device__ float g_y[(size_t)NEXP * CAP * DDIM];

// ---------------- helpers ----------------
__device__ __forceinline__ float rn_tf32(float x) {
    float r; asm("cvt.rna.tf32.f32 %0, %1;" : "=f"(r) : "f"(x)); return r;
}
__device__ __forceinline__ uint32_t smem_u32(const void* p) {
    uint32_t a;
    asm("{ .reg .u64 t; cvta.to.shared.u64 t, %1; cvt.u32.u64 %0, t; }" : "=r"(a) : "l"(p));
    return a;
}

#define CPA(dst, src, n) asm volatile("cp.async.cg.shared.global [%0], [%1], 16, %2;" :: "r"(dst), "l"(src), "r"(n) : "memory")
#define CPA_COMMIT()     asm volatile("cp.async.commit_group;" ::: "memory")
#define CPA_WAIT0()      asm volatile("cp.async.wait_group 0;" ::: "memory")

#define MMA_TF32(d, a, b) \
    asm volatile("mma.sync.aligned.m16n8k8.row.col.f32.tf32.tf32.f32 " \
        "{%0,%1,%2,%3}, {%4,%5,%6,%7}, {%8,%9}, {%0,%1,%2,%3};" \
        : "+f"((d)[0]), "+f"((d)[1]), "+f"((d)[2]), "+f"((d)[3]) \
        : "r"((a)[0]), "r"((a)[1]), "r"((a)[2]), "r"((a)[3]), "r"((b)[0]), "r"((b)[1]))

// ---------------- kernel 0: reset ----------------
__global__ void reset_kernel() {
    if (threadIdx.x < NEXP) g_count[threadIdx.x] = 0;
}

// ---------------- kernel 1: router ----------------
__global__ void router_kernel(const float* __restrict__ X, const float* __restrict__ RW) {
    __shared__ float sW[NEXP * DDIM];
    const int tid = threadIdx.x;
    for (int i = tid; i < NEXP * DDIM; i += 128) {
        int d = i >> 3, e = i & 7;
        sW[e * DDIM + d] = RW[i];
    }
    __syncthreads();
    const int warp = tid >> 5, lane = tid & 31;
    const int t = blockIdx.x * 4 + warp;
    const float* xr = X + (size_t)t * DDIM;
    float acc[NEXP];
#pragma unroll
    for (int e = 0; e < NEXP; e++) acc[e] = 0.f;
    for (int d = lane; d < DDIM; d += 32) {
        float xv = xr[d];
#pragma unroll
        for (int e = 0; e < NEXP; e++) acc[e] += xv * sW[e * DDIM + d];
    }
#pragma unroll
    for (int e = 0; e < NEXP; e++)
#pragma unroll
        for (int off = 16; off > 0; off >>= 1)
            acc[e] += __shfl_xor_sync(0xFFFFFFFFu, acc[e], off);
    if (lane == 0) {
        int i0 = 0; float s0 = acc[0];
#pragma unroll
        for (int e = 1; e < NEXP; e++) if (acc[e] > s0) { s0 = acc[e]; i0 = e; }
        int i1 = -1; float s1 = -INFINITY;
#pragma unroll
        for (int e = 0; e < NEXP; e++) if (e != i0 && acc[e] > s1) { s1 = acc[e]; i1 = e; }
        float w0 = 1.f / (1.f + expf(s1 - s0));
        float w1 = 1.f - w0;
        int p0 = atomicAdd(&g_count[i0], 1);
        int p1 = atomicAdd(&g_count[i1], 1);
        g_tok[i0 * CAP + p0] = t;
        g_tok[i1 * CAP + p1] = t;
        g_slot[2 * t + 0] = i0 * CAP + p0;  g_wt[2 * t + 0] = w0;
        g_slot[2 * t + 1] = i1 * CAP + p1;  g_wt[2 * t + 1] = w1;
    }
}

// ---------------- kernel 1b/1c: round to tf32 ----------------
__global__ void roundx_kernel(const float* __restrict__ X) {
    size_t i = (size_t)blockIdx.x * 256 + threadIdx.x;
    float4 v = ((const float4*)X)[i];
    v.x = rn_tf32(v.x); v.y = rn_tf32(v.y); v.z = rn_tf32(v.z); v.w = rn_tf32(v.w);
    ((float4*)g_xr)[i] = v;
}
__global__ void roundw_kernel(const float* __restrict__ Wg,
                              const float* __restrict__ Wu,
                              const float* __restrict__ Wd) {
    size_t i = (size_t)blockIdx.x * 256 + threadIdx.x;
    float4 a = ((const float4*)Wg)[i];
    a.x = rn_tf32(a.x); a.y = rn_tf32(a.y); a.z = rn_tf32(a.z); a.w = rn_tf32(a.w);
    ((float4*)g_wgr)[i] = a;
    float4 b = ((const float4*)Wu)[i];
    b.x = rn_tf32(b.x); b.y = rn_tf32(b.y); b.z = rn_tf32(b.z); b.w = rn_tf32(b.w);
    ((float4*)g_wur)[i] = b;
    float4 c = ((const float4*)Wd)[i];
    c.x = rn_tf32(c.x); c.y = rn_tf32(c.y); c.z = rn_tf32(c.z); c.w = rn_tf32(c.w);
    ((float4*)g_wdr)[i] = c;
}

// ================= tf32 mma.sync GEMMs =================
// A smem [m][k] rows of 128B, chunk swizzle c^=(r&7).
// B smem [k][n] rows of 512B/1024B, chunk swizzle c^=2*(k&3).

__device__ __forceinline__ void load_frag_a2(
    const float* A, int k8, int wm, int lr, int lc, uint32_t fa[2][4]) {
#pragma unroll
    for (int mi = 0; mi < 2; mi++) {
        const int r0 = wm * 32 + mi * 16 + lr;
#pragma unroll
        for (int h = 0; h < 2; h++) {
            const int cx = (((2 * k8 + h) ^ lr) << 2) + lc;
            fa[mi][h * 2 + 0] = __float_as_uint(A[r0 * 32 + cx]);
            fa[mi][h * 2 + 1] = __float_as_uint(A[(r0 + 8) * 32 + cx]);
        }
    }
}
__device__ __forceinline__ void load_frag_b4(
    const float* B, int k8, int wn, int lr, int lc, uint32_t fb[4][2]) {
#pragma unroll
    for (int ni = 0; ni < 4; ni++) {
        const int c = wn * 8 + ni * 2 + (lr >> 2);
        const int bx = ((c ^ (lc << 1)) << 2) + (lr & 3);
#pragma unroll
        for (int h = 0; h < 2; h++)
            fb[ni][h] = __float_as_uint(B[(k8 * 8 + lc + 4 * h) * 128 + bx]);
    }
}
// 256-wide B tile (row 1024B), 8 n-subtiles per warp
__device__ __forceinline__ void load_frag_b8w(
    const float* B, int k8, int wn, int lr, int lc, uint32_t fb[8][2]) {
#pragma unroll
    for (int ni = 0; ni < 8; ni++) {
        const int c = wn * 16 + ni * 2 + (lr >> 2);
        const int bx = ((c ^ (lc << 1)) << 2) + (lr & 3);
#pragma unroll
        for (int h = 0; h < 2; h++)
            fb[ni][h] = __float_as_uint(B[(k8 * 8 + lc + 4 * h) * 256 + bx]);
    }
}

// ---------------- kernel 2: fused gate+up + SiLU (CTA 64x128, 2-stage, 80KB, 2 CTA/SM) ----------------
__global__ void __launch_bounds__(256, 2)
gateup_mma_kernel() {
    extern __shared__ float smem[];
    float* As  = smem;              // 2 stages x 2048 floats
    float* Bgs = smem + 4096;       // 2 stages x 4096
    float* Bus = smem + 12288;      // 2 stages x 4096

    const int e = blockIdx.z;
    const int cnt = g_count[e];
    const int m0 = blockIdx.x * 64;
    if (m0 >= cnt) return;
    const int n0 = blockIdx.y * 128;

    const int tid = threadIdx.x, wid = tid >> 5, lane = tid & 31;
    const int wm = wid & 1, wn = wid >> 1;
    const int lr = lane >> 2, lc = lane & 3;

    const int ar = tid >> 2;
    const bool av = (m0 + ar) < cnt;
    const float* arow = g_xr + (size_t)(av ? g_tok[e * CAP + m0 + ar] : 0) * DDIM;
    const int an = av ? 16 : 0;
    uint32_t aoff[2]; int ac[2];
#pragma unroll
    for (int i = 0; i < 2; i++) {
        int c = (tid & 3) + 4 * i;
        ac[i] = c;
        aoff[i] = (uint32_t)(ar * 128 + ((c ^ (ar & 7)) << 4));
    }
    const int bk = tid >> 3;
    const float* grow = g_wgr + ((size_t)e * DDIM + bk) * FDIM + n0;
    const float* urow = g_wur + ((size_t)e * DDIM + bk) * FDIM + n0;
    uint32_t boff[4]; int bc[4];
#pragma unroll
    for (int i = 0; i < 4; i++) {
        int c = (tid & 7) + 8 * i;
        bc[i] = c;
        boff[i] = (uint32_t)(bk * 512 + ((c ^ ((bk & 3) << 1)) << 4));
    }

    const uint32_t sA = smem_u32(As), sG = smem_u32(Bgs), sU = smem_u32(Bus);

    float accg[2][4][4], accu[2][4][4];
#pragma unroll
    for (int mi = 0; mi < 2; mi++)
#pragma unroll
        for (int ni = 0; ni < 4; ni++)
#pragma unroll
            for (int q = 0; q < 4; q++) { accg[mi][ni][q] = 0.f; accu[mi][ni][q] = 0.f; }

    const int KT = DDIM / 32;   // 32

#define GU_PREFETCH(s) do { \
    int _buf = (s) & 1; \
    uint32_t _da = sA + _buf * 8192, _dg = sG + _buf * 16384, _du = sU + _buf * 16384; \
    const float* _ap = arow + (s) * 32; \
    const float* _gp = grow + (size_t)(s) * 32 * FDIM; \
    const float* _up = urow + (size_t)(s) * 32 * FDIM; \
    _Pragma("unroll") \
    for (int _i = 0; _i < 2; _i++) CPA(_da + aoff[_i], _ap + ac[_i] * 4, an); \
    _Pragma("unroll") \
    for (int _i = 0; _i < 4; _i++) { \
        CPA(_dg + boff[_i], _gp + bc[_i] * 4, 16); \
        CPA(_du + boff[_i], _up + bc[_i] * 4, 16); \
    } } while (0)

    GU_PREFETCH(0); CPA_COMMIT();

    for (int s = 0; s < KT; s++) {
        CPA_WAIT0();
        __syncthreads();            // single barrier per stage
        if (s + 1 < KT) { GU_PREFETCH(s + 1); }
        CPA_COMMIT();
        const int buf = s & 1;
        const float* A = As  + buf * 2048;
        const float* G = Bgs + buf * 4096;
        const float* U = Bus + buf * 4096;
        uint32_t fa[2][2][4], fg[2][4][2], fu[2][4][2];
        load_frag_a2(A, 0, wm, lr, lc, fa[0]);
        load_frag_b4(G, 0, wn, lr, lc, fg[0]);
        load_frag_b4(U, 0, wn, lr, lc, fu[0]);
#pragma unroll
        for (int k8 = 0; k8 < 4; k8++) {
            const int cur = k8 & 1, nxt = (k8 + 1) & 1;
            if (k8 < 3) {
                load_frag_a2(A, k8 + 1, wm, lr, lc, fa[nxt]);
                load_frag_b4(G, k8 + 1, wn, lr, lc, fg[nxt]);
                load_frag_b4(U, k8 + 1, wn, lr, lc, fu[nxt]);
            }
#pragma unroll
            for (int ni = 0; ni < 4; ni++)
#pragma unroll
                for (int mi = 0; mi < 2; mi++) {
                    MMA_TF32(accg[mi][ni], fa[cur][mi], fg[cur][ni]);
                    MMA_TF32(accu[mi][ni], fa[cur][mi], fu[cur][ni]);
                }
        }
    }

    // epilogue: act = rn_tf32(silu(g)*u)
#pragma unroll
    for (int mi = 0; mi < 2; mi++) {
        const int r = wm * 32 + mi * 16 + lr;
        const size_t row0 = (size_t)e * CAP + m0 + r;
#pragma unroll
        for (int ni = 0; ni < 4; ni++) {
            const int col = n0 + wn * 32 + ni * 8 + 2 * lc;
            if (m0 + r < cnt) {
                float g0 = accg[mi][ni][0], g1 = accg[mi][ni][1];
                float2 v;
                v.x = rn_tf32((g0 / (1.f + __expf(-g0))) * accu[mi][ni][0]);
                v.y = rn_tf32((g1 / (1.f + __expf(-g1))) * accu[mi][ni][1]);
                *(float2*)&g_act[row0 * FDIM + col] = v;
            }
            if (m0 + r + 8 < cnt) {
                float g2 = accg[mi][ni][2], g3 = accg[mi][ni][3];
                float2 v;
                v.x = rn_tf32((g2 / (1.f + __expf(-g2))) * accu[mi][ni][2]);
                v.y = rn_tf32((g3 / (1.f + __expf(-g3))) * accu[mi][ni][3]);
                *(float2*)&g_act[(row0 + 8) * FDIM + col] = v;
            }
        }
    }
}

// ---------------- kernel 3: down GEMM (CTA 64x256x32, warp 32x64, 2-stage, 80KB, 2 CTA/SM) ----------------
__global__ void __launch_bounds__(256, 2)
down_mma_kernel() {
    extern __shared__ float smem[];
    float* As = smem;               // 2 stages x 2048 floats (8KB each)
    float* Bs = smem + 4096;        // 2 stages x 8192 floats (32KB each)

    const int e = blockIdx.z;
    const int cnt = g_count[e];
    const int m0 = blockIdx.x * 64;
    if (m0 >= cnt) return;
    const int n0 = blockIdx.y * 256;

    const int tid = threadIdx.x, wid = tid >> 5, lane = tid & 31;
    const int wm = wid & 1, wn = wid >> 1;   // wn 0..3, 64-col slabs
    const int lr = lane >> 2, lc = lane & 3;

    // A: row = tid>>2 (0..63), 2 chunks of 16B
    const int ar = tid >> 2;
    const bool av = (m0 + ar) < cnt;
    const float* arow = g_act + ((size_t)e * CAP + m0 + (av ? ar : 0)) * FDIM;
    const int an = av ? 16 : 0;
    uint32_t aoff[2]; int ac[2];
#pragma unroll
    for (int i = 0; i < 2; i++) {
        int c = (tid & 3) + 4 * i;
        ac[i] = c;
        aoff[i] = (uint32_t)(ar * 128 + ((c ^ (ar & 7)) << 4));
    }
    // B: k-row = tid>>3 (0..31), 8 chunks along n (256 floats = 64 chunks, row 1024B)
    const int bk = tid >> 3;
    const float* brow = g_wdr + ((size_t)e * FDIM + bk) * DDIM + n0;
    uint32_t boff[8]; int bc[8];
#pragma unroll
    for (int i = 0; i < 8; i++) {
        int c = (tid & 7) + 8 * i;
        bc[i] = c;
        boff[i] = (uint32_t)(bk * 1024 + ((c ^ ((bk & 3) << 1)) << 4));
    }

    const uint32_t sA = smem_u32(As), sB = smem_u32(Bs);

    float acc[2][8][4];
#pragma unroll
    for (int mi = 0; mi < 2; mi++)
#pragma unroll
        for (int ni = 0; ni < 8; ni++)
#pragma unroll
            for (int q = 0; q < 4; q++) acc[mi][ni][q] = 0.f;

    const int KT = FDIM / 32;   // 88

#define DN_PREFETCH(s) do { \
    int _buf = (s) & 1; \
    uint32_t _da = sA + _buf * 8192, _db = sB + _buf * 32768; \
    const float* _ap = arow + (s) * 32; \
    const float* _bp = brow + (size_t)(s) * 32 * DDIM; \
    _Pragma("unroll") \
    for (int _i = 0; _i < 2; _i++) CPA(_da + aoff[_i], _ap + ac[_i] * 4, an); \
    _Pragma("unroll") \
    for (int _i = 0; _i < 8; _i++) CPA(_db + boff[_i], _bp + bc[_i] * 4, 16); \
    } while (0)

    DN_PREFETCH(0); CPA_COMMIT();

    for (int s = 0; s < KT; s++) {
        CPA_WAIT0();
        __syncthreads();            // single barrier per stage
        if (s + 1 < KT) { DN_PREFETCH(s + 1); }
        CPA_COMMIT();
        const int buf = s & 1;
        const float* A = As + buf * 2048;
        const float* B = Bs + buf * 8192;
        uint32_t fa[2][2][4];
        load_frag_a2(A, 0, wm, lr, lc, fa[0]);
#pragma unroll
        for (int k8 = 0; k8 < 4; k8++) {
            const int cur = k8 & 1, nxt = (k8 + 1) & 1;
            uint32_t fb[8][2];
            load_frag_b8w(B, k8, wn, lr, lc, fb);
            if (k8 < 3) load_frag_a2(A, k8 + 1, wm, lr, lc, fa[nxt]);
#pragma unroll
            for (int ni = 0; ni < 8; ni++)
#pragma unroll
                for (int mi = 0; mi < 2; mi++)
                    MMA_TF32(acc[mi][ni], fa[cur][mi], fb[ni]);
        }
    }

#pragma unroll
    for (int mi = 0; mi < 2; mi++) {
        const int r = wm * 32 + mi * 16 + lr;
        const size_t row0 = (size_t)e * CAP + m0 + r;
#pragma unroll
        for (int ni = 0; ni < 8; ni++) {
            const int col = n0 + wn * 64 + ni * 8 + 2 * lc;
            if (m0 + r < cnt) {
                float2 v; v.x = acc[mi][ni][0]; v.y = acc[mi][ni][1];
                *(float2*)&g_y[row0 * DDIM + col] = v;
            }
            if (m0 + r + 8 < cnt) {
                float2 v; v.x = acc[mi][ni][2]; v.y = acc[mi][ni][3];
                *(float2*)&g_y[(row0 + 8) * DDIM + col] = v;
            }
        }
    }
}

// ---------------- kernel 4: weighted combine ----------------
__global__ void combine_kernel(float* __restrict__ out) {
    const int g = blockIdx.x * blockDim.x + threadIdx.x;
    const int t = g >> 8;
    const int c = g & 255;
    const int s0 = g_slot[2 * t], s1 = g_slot[2 * t + 1];
    const float w0 = g_wt[2 * t], w1 = g_wt[2 * t + 1];
    const float4* Y = (const float4*)g_y;
    float4 a = Y[(size_t)s0 * 256 + c];
    float4 b = Y[(size_t)s1 * 256 + c];
    float4 o;
    o.x = w0 * a.x + w1 * b.x;
    o.y = w0 * a.y + w1 * b.y;
    o.z = w0 * a.z + w1 * b.z;
    o.w = w0 * a.w + w1 * b.w;
    ((float4*)out)[g] = o;
}

// ---------------- launch ----------------
extern "C" void kernel_launch(void* const* d_in, const int* in_sizes, int n_in,
                              void* d_out, int out_size) {
    const float* x  = (const float*)d_in[0];
    const float* rw = (const float*)d_in[1];
    const float* wg = (const float*)d_in[2];
    const float* wu = (const float*)d_in[3];
    const float* wd = (const float*)d_in[4];
    float* out = (float*)d_out;

    cudaFuncSetAttribute(gateup_mma_kernel, cudaFuncAttributeMaxDynamicSharedMemorySize, 81920);
    cudaFuncSetAttribute(down_mma_kernel,   cudaFuncAttributeMaxDynamicSharedMemorySize, 81920);

    reset_kernel<<<1, 32>>>();
    router_kernel<<<NTOK / 4, 128>>>(x, rw);

    roundx_kernel<<<(NTOK * DDIM / 4) / 256, 256>>>(x);
    roundw_kernel<<<(NEXP * DDIM * FDIM / 4) / 256, 256>>>(wg, wu, wd);

    gateup_mma_kernel<<<dim3(CAP / 64, FDIM / 128, NEXP), 256, 81920>>>();
    down_mma_kernel<<<dim3(CAP / 64, DDIM / 256, NEXP), 256, 81920>>>();

    combine_kernel<<<(NTOK * 256) / 256, 256>>>(out);
}